// round 10
// baseline (speedup 1.0000x reference)
#include <cuda_runtime.h>
#include <cuda_bf16.h>
#include <cstdint>

#define B_ROWS 16384
#define F_DIM  512
#define H_DIM  256
#define E_NUM  8
#define OUT_DIM 32
#define DA     8
#define TM     64
#define NTILES (B_ROWS / TM)   // 256

#define BSTR 20    // b32 stride, 32-bf16 staged rows (16 words + 4 pad); 20%8=4 -> ldsm conflict-free
#define HSTR 132   // b32 stride, 256-bf16 h rows (128 words + 4 pad)

// ---------------- device scratch ----------------
__device__ int g_counts[E_NUM];
__device__ int g_bucket[E_NUM][B_ROWS];

__device__ __align__(16) __nv_bfloat16 g_W1T_hi[E_NUM][H_DIM][F_DIM];
__device__ __align__(16) __nv_bfloat16 g_W1T_lo[E_NUM][H_DIM][F_DIM];
__device__ __align__(16) __nv_bfloat16 g_W2T_hi[E_NUM][H_DIM][H_DIM];
__device__ __align__(16) __nv_bfloat16 g_W2T_lo[E_NUM][H_DIM][H_DIM];
__device__ __align__(16) __nv_bfloat16 g_W3T_hi[E_NUM][OUT_DIM][H_DIM];
__device__ __align__(16) __nv_bfloat16 g_W3T_lo[E_NUM][OUT_DIM][H_DIM];

__device__ __forceinline__ void split1(float x, __nv_bfloat16& h, __nv_bfloat16& l) {
    h = __float2bfloat16_rn(x);
    l = __float2bfloat16_rn(x - __bfloat162float(h));
}
__device__ __forceinline__ uint32_t packbf(__nv_bfloat16 a, __nv_bfloat16 b) {
    __nv_bfloat162 t(a, b);
    return *reinterpret_cast<uint32_t*>(&t);
}
__device__ __forceinline__ void split_pack(float v0, float v1, uint32_t& hp, uint32_t& lp) {
    __nv_bfloat16 h0, l0, h1, l1;
    split1(v0, h0, l0); split1(v1, h1, l1);
    hp = packbf(h0, h1);
    lp = packbf(l0, l1);
}
__device__ __forceinline__ uint32_t smem_u32(const void* p) {
    uint32_t a;
    asm("{ .reg .u64 t; cvta.to.shared.u64 t, %1; cvt.u32.u64 %0, t; }" : "=r"(a) : "l"(p));
    return a;
}
__device__ __forceinline__ void cpasync16(uint32_t dst, const void* src) {
    asm volatile("cp.async.cg.shared.global [%0], [%1], 16;" :: "r"(dst), "l"(src));
}
#define CP_COMMIT() asm volatile("cp.async.commit_group;")
#define CP_WAIT0()  asm volatile("cp.async.wait_group 0;")

__device__ __forceinline__ void mma16816(float* d, const uint32_t* a, const uint32_t* b) {
    asm volatile("mma.sync.aligned.m16n8k16.row.col.f32.bf16.bf16.f32 "
        "{%0,%1,%2,%3}, {%4,%5,%6,%7}, {%8,%9}, {%0,%1,%2,%3};"
        : "+f"(d[0]), "+f"(d[1]), "+f"(d[2]), "+f"(d[3])
        : "r"(a[0]), "r"(a[1]), "r"(a[2]), "r"(a[3]), "r"(b[0]), "r"(b[1]));
}
__device__ __forceinline__ void ldsm_x4(uint32_t* r, uint32_t addr) {
    asm volatile("ldmatrix.sync.aligned.m8n8.x4.shared.b16 {%0,%1,%2,%3}, [%4];"
        : "=r"(r[0]), "=r"(r[1]), "=r"(r[2]), "=r"(r[3]) : "r"(addr));
}

// Warp-tile (32 rows x 64 cols) over NKS*16 K, bf16x3 split, ldmatrix frags.
template<int LDA, int LDB, int NKS>
__device__ __forceinline__ void mma_chunk_ldsm(
    float acc[2][8][4],
    uint32_t aHi, uint32_t aLo, uint32_t bHi, uint32_t bLo)
{
    #pragma unroll
    for (int ks = 0; ks < NKS; ks++) {
        uint32_t ah[2][4], al[2][4];
        #pragma unroll
        for (int mi = 0; mi < 2; mi++) {
            ldsm_x4(ah[mi], aHi + mi * (16 * LDA * 4) + ks * 32);
            ldsm_x4(al[mi], aLo + mi * (16 * LDA * 4) + ks * 32);
        }
        #pragma unroll
        for (int p = 0; p < 4; p++) {
            uint32_t bh[4], bl[4];
            ldsm_x4(bh, bHi + p * (16 * LDB * 4) + ks * 32);
            ldsm_x4(bl, bLo + p * (16 * LDB * 4) + ks * 32);
            #pragma unroll
            for (int q = 0; q < 2; q++) {
                const int ni = p * 2 + q;
                #pragma unroll
                for (int mi = 0; mi < 2; mi++) {
                    mma16816(acc[mi][ni], ah[mi], bh + q * 2);
                    mma16816(acc[mi][ni], ah[mi], bl + q * 2);
                    mma16816(acc[mi][ni], al[mi], bh + q * 2);
                }
            }
        }
    }
}

// ---------------- prep kernels ----------------
__global__ void zero_counts_kernel() {
    if (threadIdx.x < E_NUM) g_counts[threadIdx.x] = 0;
}
__global__ void scatter_kernel(const int* __restrict__ ma) {
    int i = blockIdx.x * blockDim.x + threadIdx.x;
    if (i < B_ROWS) {
        int e = ma[i];
        int p = atomicAdd(&g_counts[e], 1);
        g_bucket[e][p] = i;
    }
}
__global__ void prep_weights(const float* __restrict__ W1,
                             const float* __restrict__ W2,
                             const float* __restrict__ W3) {
    int z = blockIdx.z, e = blockIdx.y;
    int Kd = (z == 0) ? F_DIM : H_DIM;
    int Nd = (z == 0) ? H_DIM : ((z == 1) ? H_DIM : OUT_DIM);
    int ntn = Nd / 32;
    int tk = (blockIdx.x / ntn) * 32;
    int tn = (blockIdx.x % ntn) * 32;
    if (tk >= Kd) return;
    const float* src = ((z == 0) ? W1 : (z == 1) ? W2 : W3) + (size_t)e * Kd * Nd;
    __nv_bfloat16* dh = (z == 0) ? &g_W1T_hi[e][0][0] : (z == 1) ? &g_W2T_hi[e][0][0] : &g_W3T_hi[e][0][0];
    __nv_bfloat16* dl = (z == 0) ? &g_W1T_lo[e][0][0] : (z == 1) ? &g_W2T_lo[e][0][0] : &g_W3T_lo[e][0][0];
    __shared__ float tile[32][33];
    int tx = threadIdx.x, ty = threadIdx.y;   // 32 x 8
    #pragma unroll
    for (int r = 0; r < 4; r++)
        tile[ty + r * 8][tx] = src[(size_t)(tk + ty + r * 8) * Nd + tn + tx];
    __syncthreads();
    #pragma unroll
    for (int r = 0; r < 4; r++) {
        int n = tn + ty + r * 8, k = tk + tx;
        float v = tile[tx][ty + r * 8];
        __nv_bfloat16 h, l; split1(v, h, l);
        dh[(size_t)n * Kd + k] = h;
        dl[(size_t)n * Kd + k] = l;
    }
}

// ---------------- smem layout (b32 words), per CTA ----------------
#define OFF_BHI  0                 // 256 rows x BSTR = 5120
#define OFF_BLO  5120              // 5120
#define OFF_HHI  10240             // 64 x HSTR = 8448
#define OFF_HLO  18688             // 8448
#define A_HI     10240             // 64 x BSTR = 1280 (aliases hHi start; A dead before h written)
#define A_LO     11520             // 1280
#define OFF_W3HI 0                 // 8 x HSTR = 1056 (aliases B region after layer 2)
#define OFF_W3LO 1056
#define OFF_IDX  27136             // 64
#define OFF_SB1  27200             // 256
#define OFF_SB2  27456             // 256
#define OFF_SB3  27712             // 8
#define SMEM_WORDS 27720           // 110880 bytes -> 2 CTAs/SM (221760 <= 228K)

// ---------------- main MMA kernel: 256 threads, 2x4 warps, 2 CTAs/SM ----------------
__global__ __launch_bounds__(256, 2)
void moe_mma_kernel(const float* __restrict__ features,
                    const float* __restrict__ b1,
                    const float* __restrict__ b2,
                    const float* __restrict__ b3,
                    float* __restrict__ out)
{
    const int e = blockIdx.y;
    const int count = g_counts[e];
    const int row0 = blockIdx.x * TM;
    if (row0 >= count) return;
    const int nrows = min(TM, count - row0);

    extern __shared__ uint32_t sm[];
    const uint32_t sb = smem_u32(sm);
    int*   sIdx = (int*)(sm + OFF_IDX);
    float* sB1  = (float*)(sm + OFF_SB1);
    float* sB2  = (float*)(sm + OFF_SB2);
    float* sB3  = (float*)(sm + OFF_SB3);
    uint32_t* hHi = sm + OFF_HHI;
    uint32_t* hLo = sm + OFF_HLO;

    const int t    = threadIdx.x;
    const int wid  = t >> 5;
    const int lane = t & 31;
    const int gid  = lane >> 2;
    const int tig  = lane & 3;
    const int wrow = wid & 1;       // 2 row-warps * 32 rows
    const int wcol = wid >> 1;      // 4 col-warps * 64 cols

    // ldmatrix per-lane byte offsets
    const int l8 = lane & 7, lq = lane >> 3;
    const int laneA_B  = ((l8 + 8 * (lq & 1)) * BSTR) * 4 + (lq >> 1) * 16;   // A in BSTR tiles
    const int laneA_H  = ((l8 + 8 * (lq & 1)) * HSTR) * 4 + (lq >> 1) * 16;   // A in h tiles
    const int laneB_B  = ((l8 + 8 * (lq >> 1)) * BSTR) * 4 + (lq & 1) * 16;   // B in BSTR tiles

    if (t < TM) sIdx[t] = g_bucket[e][row0 + min(t, nrows - 1)];
    sB1[t] = b1[e * H_DIM + t];
    sB2[t] = b2[e * H_DIM + t];
    if (t < DA) sB3[t] = b3[e * OUT_DIM + t];
    __syncthreads();

    // staging roles (256 threads)
    const int arow = t >> 2, aseg = t & 3;     // A: 64 rows x 4 segs of 8 floats
    const int brow = t;                        // B: 256 rows, 1 row/thread (32 bf16)
    const float* frow = features + (size_t)sIdx[arow] * F_DIM;

    const __nv_bfloat16* w1h = &g_W1T_hi[e][0][0];
    const __nv_bfloat16* w1l = &g_W1T_lo[e][0][0];
    const __nv_bfloat16* w2h = &g_W2T_hi[e][0][0];
    const __nv_bfloat16* w2l = &g_W2T_lo[e][0][0];
    const __nv_bfloat16* w3h = &g_W3T_hi[e][0][0];
    const __nv_bfloat16* w3l = &g_W3T_lo[e][0][0];

    float acc[2][8][4];
    #pragma unroll
    for (int mi = 0; mi < 2; mi++)
        #pragma unroll
        for (int ni = 0; ni < 8; ni++)
            #pragma unroll
            for (int c = 0; c < 4; c++) acc[mi][ni][c] = 0.f;

    auto issueB1 = [&](int kc) {
        const __nv_bfloat16* sh = w1h + (size_t)brow * F_DIM + kc * 32;
        const __nv_bfloat16* sl = w1l + (size_t)brow * F_DIM + kc * 32;
        uint32_t dh = sb + (OFF_BHI + brow * BSTR) * 4;
        uint32_t dl = sb + (OFF_BLO + brow * BSTR) * 4;
        #pragma unroll
        for (int c = 0; c < 4; c++) {
            cpasync16(dh + c * 16, sh + c * 8);
            cpasync16(dl + c * 16, sl + c * 8);
        }
        CP_COMMIT();
    };
    auto issueB2 = [&](int kc) {
        const __nv_bfloat16* sh = w2h + (size_t)brow * H_DIM + kc * 32;
        const __nv_bfloat16* sl = w2l + (size_t)brow * H_DIM + kc * 32;
        uint32_t dh = sb + (OFF_BHI + brow * BSTR) * 4;
        uint32_t dl = sb + (OFF_BLO + brow * BSTR) * 4;
        #pragma unroll
        for (int c = 0; c < 4; c++) {
            cpasync16(dh + c * 16, sh + c * 8);
            cpasync16(dl + c * 16, sl + c * 8);
        }
        CP_COMMIT();
    };
    auto stageA = [&](const float4* v4) {
        uint32_t* dH = sm + A_HI + arow * BSTR + aseg * 4;
        uint32_t* dL = sm + A_LO + arow * BSTR + aseg * 4;
        #pragma unroll
        for (int j = 0; j < 2; j++) {
            uint32_t h0, l0, h1, l1;
            split_pack(v4[j].x, v4[j].y, h0, l0);
            split_pack(v4[j].z, v4[j].w, h1, l1);
            dH[j * 2] = h0; dH[j * 2 + 1] = h1;
            dL[j * 2] = l0; dL[j * 2 + 1] = l1;
        }
    };

    // ============ Layer 1: 16 chunks of K=32 (single-buffered; CTA pairing hides waits) ============
    float4 v4[2];
    {
        const float* src = frow + aseg * 8;
        v4[0] = *(const float4*)(src);
        v4[1] = *(const float4*)(src + 4);
    }
    #pragma unroll 1
    for (int kc = 0; kc < 16; kc++) {
        __syncthreads();          // previous chunk's MMA reads of A/B complete
        issueB1(kc);
        stageA(v4);
        if (kc < 15) {            // prefetch next A chunk into registers
            const float* src = frow + (kc + 1) * 32 + aseg * 8;
            v4[0] = *(const float4*)(src);
            v4[1] = *(const float4*)(src + 4);
        }
        CP_WAIT0();
        __syncthreads();          // chunk visible to all warps
        mma_chunk_ldsm<BSTR, BSTR, 2>(acc,
            sb + (A_HI + wrow * 32 * BSTR) * 4 + laneA_B,
            sb + (A_LO + wrow * 32 * BSTR) * 4 + laneA_B,
            sb + (OFF_BHI + wcol * 64 * BSTR) * 4 + laneB_B,
            sb + (OFF_BLO + wcol * 64 * BSTR) * 4 + laneB_B);
    }
    __syncthreads();   // layer-1 MMA done: safe to write h (aliases A)

    // epilogue 1: relu + bias -> h
    #pragma unroll
    for (int mi = 0; mi < 2; mi++) {
        int r0 = wrow * 32 + mi * 16 + gid;
        #pragma unroll
        for (int ni = 0; ni < 8; ni++) {
            int col = wcol * 64 + ni * 8 + 2 * tig;
            int cp  = col >> 1;
            float v0 = fmaxf(acc[mi][ni][0] + sB1[col], 0.f);
            float v1 = fmaxf(acc[mi][ni][1] + sB1[col + 1], 0.f);
            float v2 = fmaxf(acc[mi][ni][2] + sB1[col], 0.f);
            float v3 = fmaxf(acc[mi][ni][3] + sB1[col + 1], 0.f);
            uint32_t hp, lp;
            split_pack(v0, v1, hp, lp);
            hHi[r0 * HSTR + cp] = hp; hLo[r0 * HSTR + cp] = lp;
            split_pack(v2, v3, hp, lp);
            hHi[(r0 + 8) * HSTR + cp] = hp; hLo[(r0 + 8) * HSTR + cp] = lp;
            acc[mi][ni][0] = 0.f; acc[mi][ni][1] = 0.f;
            acc[mi][ni][2] = 0.f; acc[mi][ni][3] = 0.f;
        }
    }

    // ============ Layer 2: 8 chunks of K=32 ============
    #pragma unroll 1
    for (int kc = 0; kc < 8; kc++) {
        __syncthreads();          // orders h writes (kc==0) / prev MMA B reads before restage
        issueB2(kc);
        CP_WAIT0();
        __syncthreads();
        mma_chunk_ldsm<HSTR, BSTR, 2>(acc,
            sb + (OFF_HHI + wrow * 32 * HSTR + kc * 16) * 4 + laneA_H,
            sb + (OFF_HLO + wrow * 32 * HSTR + kc * 16) * 4 + laneA_H,
            sb + (OFF_BHI + wcol * 64 * BSTR) * 4 + laneB_B,
            sb + (OFF_BLO + wcol * 64 * BSTR) * 4 + laneB_B);
    }
    __syncthreads();   // layer-2 MMA done: safe to overwrite h and B region (W3)

    // stage W3T rows 0..7 (first 8 out cols), K=256, into B region
    if (t < 64) {
        int n = t >> 3, i = (t & 7) * 16;
        const uint4* sh = (const uint4*)(w3h + (size_t)n * H_DIM + i * 2);
        const uint4* sl = (const uint4*)(w3l + (size_t)n * H_DIM + i * 2);
        #pragma unroll
        for (int j = 0; j < 4; j++) {
            *(uint4*)&sm[OFF_W3HI + n * HSTR + i + j * 4] = sh[j];
            *(uint4*)&sm[OFF_W3LO + n * HSTR + i + j * 4] = sl[j];
        }
    }

    // epilogue 2: relu + bias -> h (overwrite)
    #pragma unroll
    for (int mi = 0; mi < 2; mi++) {
        int r0 = wrow * 32 + mi * 16 + gid;
        #pragma unroll
        for (int ni = 0; ni < 8; ni++) {
            int col = wcol * 64 + ni * 8 + 2 * tig;
            int cp  = col >> 1;
            float v0 = fmaxf(acc[mi][ni][0] + sB2[col], 0.f);
            float v1 = fmaxf(acc[mi][ni][1] + sB2[col + 1], 0.f);
            float v2 = fmaxf(acc[mi][ni][2] + sB2[col], 0.f);
            float v3 = fmaxf(acc[mi][ni][3] + sB2[col + 1], 0.f);
            uint32_t hp, lp;
            split_pack(v0, v1, hp, lp);
            hHi[r0 * HSTR + cp] = hp; hLo[r0 * HSTR + cp] = lp;
            split_pack(v2, v3, hp, lp);
            hHi[(r0 + 8) * HSTR + cp] = hp; hLo[(r0 + 8) * HSTR + cp] = lp;
        }
    }
    __syncthreads();

    // ============ Layer 3: y = h2 @ W3[:, :8] + b3 (warps 0..3 cover 64 rows) ============
    if (wid < 4) {
        float acc3[4] = {0.f, 0.f, 0.f, 0.f};
        const uint32_t* pAh = hHi + wid * 16 * HSTR;
        const uint32_t* pAl = hLo + wid * 16 * HSTR;
        const uint32_t* w3H = sm + OFF_W3HI;
        const uint32_t* w3L = sm + OFF_W3LO;
        #pragma unroll
        for (int ks = 0; ks < 16; ks++) {
            const int kb = ks * 8 + tig;
            uint32_t ah[4], al[4];
            ah[0] = pAh[gid * HSTR + kb];       ah[1] = pAh[(gid + 8) * HSTR + kb];
            ah[2] = pAh[gid * HSTR + kb + 4];   ah[3] = pAh[(gid + 8) * HSTR + kb + 4];
            al[0] = pAl[gid * HSTR + kb];       al[1] = pAl[(gid + 8) * HSTR + kb];
            al[2] = pAl[gid * HSTR + kb + 4];   al[3] = pAl[(gid + 8) * HSTR + kb + 4];
            uint32_t bh[2] = { w3H[gid * HSTR + kb], w3H[gid * HSTR + kb + 4] };
            uint32_t bl[2] = { w3L[gid * HSTR + kb], w3L[gid * HSTR + kb + 4] };
            mma16816(acc3, ah, bh);
            mma16816(acc3, ah, bl);
            mma16816(acc3, al, bh);
        }
        int r0 = wid * 16 + gid;
        int c  = 2 * tig;
        if (r0 < nrows) {
            float* o = out + (size_t)sIdx[r0] * DA + c;
            o[0] = acc3[0] + sB3[c];
            o[1] = acc3[1] + sB3[c + 1];
        }
        if (r0 + 8 < nrows) {
            float* o = out + (size_t)sIdx[r0 + 8] * DA + c;
            o[0] = acc3[2] + sB3[c];
            o[1] = acc3[3] + sB3[c + 1];
        }
    }
}

extern "C" void kernel_launch(void* const* d_in, const int* in_sizes, int n_in,
                              void* d_out, int out_size)
{
    const float* features = (const float*)d_in[0];
    const float* W1 = (const float*)d_in[1];
    const float* b1 = (const float*)d_in[2];
    const float* W2 = (const float*)d_in[3];
    const float* b2 = (const float*)d_in[4];
    const float* W3 = (const float*)d_in[5];
    const float* b3 = (const float*)d_in[6];
    const int*   ma = (const int*)d_in[7];
    float* out = (float*)d_out;

    cudaFuncSetAttribute(moe_mma_kernel, cudaFuncAttributeMaxDynamicSharedMemorySize,
                         SMEM_WORDS * 4);

    zero_counts_kernel<<<1, 32>>>();
    scatter_kernel<<<B_ROWS / 256, 256>>>(ma);
    prep_weights<<<dim3(128, E_NUM, 3), dim3(32, 8)>>>(W1, W2, W3);
    moe_mma_kernel<<<dim3(NTILES, E_NUM), 256, SMEM_WORDS * 4>>>(features, b1, b2, b3, out);
}

// round 11
// speedup vs baseline: 2.0793x; 2.0793x over previous
#include <cuda_runtime.h>
#include <cuda_bf16.h>
#include <cstdint>

#define B_ROWS 16384
#define F_DIM  512
#define H_DIM  256
#define E_NUM  8
#define OUT_DIM 32
#define DA     8
#define TM     128
#define NTILES (B_ROWS / TM)   // 128

#define ASTR 36    // b32 stride, 64-bf16 rows (32 words + 4 pad)
#define B2STR 20   // b32 stride, 32-bf16 rows (16 words + 4 pad)
#define HSTR 132   // b32 stride, 256-bf16 h rows (128 words + 4 pad)

// ---------------- device scratch ----------------
__device__ int g_counts[E_NUM];
__device__ int g_bucket[E_NUM][B_ROWS];

__device__ __align__(16) __nv_bfloat16 g_W1T_hi[E_NUM][H_DIM][F_DIM];
__device__ __align__(16) __nv_bfloat16 g_W1T_lo[E_NUM][H_DIM][F_DIM];
__device__ __align__(16) __nv_bfloat16 g_W2T_hi[E_NUM][H_DIM][H_DIM];
__device__ __align__(16) __nv_bfloat16 g_W2T_lo[E_NUM][H_DIM][H_DIM];
__device__ __align__(16) __nv_bfloat16 g_W3T_hi[E_NUM][OUT_DIM][H_DIM];
__device__ __align__(16) __nv_bfloat16 g_W3T_lo[E_NUM][OUT_DIM][H_DIM];

__device__ __forceinline__ void split1(float x, __nv_bfloat16& h, __nv_bfloat16& l) {
    h = __float2bfloat16_rn(x);
    l = __float2bfloat16_rn(x - __bfloat162float(h));
}
__device__ __forceinline__ uint32_t packbf(__nv_bfloat16 a, __nv_bfloat16 b) {
    __nv_bfloat162 t(a, b);
    return *reinterpret_cast<uint32_t*>(&t);
}
__device__ __forceinline__ void split_pack(float v0, float v1, uint32_t& hp, uint32_t& lp) {
    __nv_bfloat16 h0, l0, h1, l1;
    split1(v0, h0, l0); split1(v1, h1, l1);
    hp = packbf(h0, h1);
    lp = packbf(l0, l1);
}
__device__ __forceinline__ uint32_t smem_u32(const void* p) {
    uint32_t a;
    asm("{ .reg .u64 t; cvta.to.shared.u64 t, %1; cvt.u32.u64 %0, t; }" : "=r"(a) : "l"(p));
    return a;
}
__device__ __forceinline__ void cpasync16(uint32_t dst, const void* src) {
    asm volatile("cp.async.cg.shared.global [%0], [%1], 16;" :: "r"(dst), "l"(src));
}
#define CP_COMMIT() asm volatile("cp.async.commit_group;")
#define CP_WAIT0()  asm volatile("cp.async.wait_group 0;")

__device__ __forceinline__ void mma16816(float* d, const uint32_t* a, const uint32_t* b) {
    asm volatile("mma.sync.aligned.m16n8k16.row.col.f32.bf16.bf16.f32 "
        "{%0,%1,%2,%3}, {%4,%5,%6,%7}, {%8,%9}, {%0,%1,%2,%3};"
        : "+f"(d[0]), "+f"(d[1]), "+f"(d[2]), "+f"(d[3])
        : "r"(a[0]), "r"(a[1]), "r"(a[2]), "r"(a[3]), "r"(b[0]), "r"(b[1]));
}
__device__ __forceinline__ void ldsm_x4(uint32_t* r, uint32_t addr) {
    asm volatile("ldmatrix.sync.aligned.m8n8.x4.shared.b16 {%0,%1,%2,%3}, [%4];"
        : "=r"(r[0]), "=r"(r[1]), "=r"(r[2]), "=r"(r[3]) : "r"(addr));
}

// Warp-tile (32 rows x 32 cols) over NKS*16 K, bf16x3 split, ldmatrix frags.
template<int LDA, int LDB, int NKS>
__device__ __forceinline__ void mma_chunk_ldsm(
    float acc[2][4][4],
    uint32_t aHi, uint32_t aLo, uint32_t bHi, uint32_t bLo)
{
    #pragma unroll
    for (int ks = 0; ks < NKS; ks++) {
        uint32_t ah[2][4], al[2][4];
        #pragma unroll
        for (int mi = 0; mi < 2; mi++) {
            ldsm_x4(ah[mi], aHi + mi * (16 * LDA * 4) + ks * 32);
            ldsm_x4(al[mi], aLo + mi * (16 * LDA * 4) + ks * 32);
        }
        #pragma unroll
        for (int p = 0; p < 2; p++) {
            uint32_t bh[4], bl[4];
            ldsm_x4(bh, bHi + p * (16 * LDB * 4) + ks * 32);
            ldsm_x4(bl, bLo + p * (16 * LDB * 4) + ks * 32);
            #pragma unroll
            for (int q = 0; q < 2; q++) {
                const int ni = p * 2 + q;
                #pragma unroll
                for (int mi = 0; mi < 2; mi++) {
                    mma16816(acc[mi][ni], ah[mi], bh + q * 2);
                    mma16816(acc[mi][ni], ah[mi], bl + q * 2);
                    mma16816(acc[mi][ni], al[mi], bh + q * 2);
                }
            }
        }
    }
}

// ---------------- prep kernels ----------------
__global__ void zero_counts_kernel() {
    if (threadIdx.x < E_NUM) g_counts[threadIdx.x] = 0;
}
__global__ void scatter_kernel(const int* __restrict__ ma) {
    int i = blockIdx.x * blockDim.x + threadIdx.x;
    if (i < B_ROWS) {
        int e = ma[i];
        int p = atomicAdd(&g_counts[e], 1);
        g_bucket[e][p] = i;
    }
}
__global__ void prep_weights(const float* __restrict__ W1,
                             const float* __restrict__ W2,
                             const float* __restrict__ W3) {
    int z = blockIdx.z, e = blockIdx.y;
    int Kd = (z == 0) ? F_DIM : H_DIM;
    int Nd = (z == 0) ? H_DIM : ((z == 1) ? H_DIM : OUT_DIM);
    int ntn = Nd / 32;
    int tk = (blockIdx.x / ntn) * 32;
    int tn = (blockIdx.x % ntn) * 32;
    if (tk >= Kd) return;
    const float* src = ((z == 0) ? W1 : (z == 1) ? W2 : W3) + (size_t)e * Kd * Nd;
    __nv_bfloat16* dh = (z == 0) ? &g_W1T_hi[e][0][0] : (z == 1) ? &g_W2T_hi[e][0][0] : &g_W3T_hi[e][0][0];
    __nv_bfloat16* dl = (z == 0) ? &g_W1T_lo[e][0][0] : (z == 1) ? &g_W2T_lo[e][0][0] : &g_W3T_lo[e][0][0];
    __shared__ float tile[32][33];
    int tx = threadIdx.x, ty = threadIdx.y;   // 32 x 8
    #pragma unroll
    for (int r = 0; r < 4; r++)
        tile[ty + r * 8][tx] = src[(size_t)(tk + ty + r * 8) * Nd + tn + tx];
    __syncthreads();
    #pragma unroll
    for (int r = 0; r < 4; r++) {
        int n = tn + ty + r * 8, k = tk + tx;
        float v = tile[tx][ty + r * 8];
        __nv_bfloat16 h, l; split1(v, h, l);
        dh[(size_t)n * Kd + k] = h;
        dl[(size_t)n * Kd + k] = l;
    }
}

// ---------------- smem layout (b32 words) ----------------
#define B1_HI(b) ((b) * 18432)
#define B1_LO(b) (B1_HI(b) + 9216)
#define A_HI(b)  (36864 + (b) * 9216)
#define A_LO(b)  (A_HI(b) + 4608)
#define OFF_HHI  0
#define OFF_HLO  16896
#define B2_HI(b) (36864 + (b) * 10240)
#define B2_LO(b) (B2_HI(b) + 5120)
#define OFF_W3HI 36864
#define OFF_W3LO (36864 + 1056)
#define OFF_IDX  57344
#define OFF_SB1  57472
#define OFF_SB2  57728
#define OFF_SB3  57984
#define SMEM_WORDS 57992     // 231968 bytes

// ---------------- main MMA kernel: 1024 threads, 4x8 warps ----------------
__global__ __launch_bounds__(1024, 1)
void moe_mma_kernel(const float* __restrict__ features,
                    const float* __restrict__ b1,
                    const float* __restrict__ b2,
                    const float* __restrict__ b3,
                    float* __restrict__ out)
{
    const int e = blockIdx.y;
    const int count = g_counts[e];
    const int row0 = blockIdx.x * TM;
    if (row0 >= count) return;
    const int nrows = min(TM, count - row0);

    extern __shared__ uint32_t sm[];
    const uint32_t sb = smem_u32(sm);
    int*   sIdx = (int*)(sm + OFF_IDX);
    float* sB1  = (float*)(sm + OFF_SB1);
    float* sB2  = (float*)(sm + OFF_SB2);
    float* sB3  = (float*)(sm + OFF_SB3);
    uint32_t* hHi = sm + OFF_HHI;
    uint32_t* hLo = sm + OFF_HLO;

    const int t    = threadIdx.x;
    const int wid  = t >> 5;
    const int lane = t & 31;
    const int gid  = lane >> 2;
    const int tig  = lane & 3;
    const int wrow = wid & 3;       // 4 row-warps * 32 rows
    const int wcol = wid >> 2;      // 8 col-warps * 32 cols

    // ldmatrix per-lane byte offsets
    const int l8 = lane & 7, lq = lane >> 3;
    const int laneA_A  = ((l8 + 8 * (lq & 1)) * ASTR)  * 4 + (lq >> 1) * 16;
    const int laneA_H  = ((l8 + 8 * (lq & 1)) * HSTR)  * 4 + (lq >> 1) * 16;
    const int laneB_A  = ((l8 + 8 * (lq >> 1)) * ASTR) * 4 + (lq & 1) * 16;
    const int laneB_B2 = ((l8 + 8 * (lq >> 1)) * B2STR) * 4 + (lq & 1) * 16;

    if (t < TM) sIdx[t] = g_bucket[e][row0 + min(t, nrows - 1)];
    if (t < H_DIM) {
        sB1[t] = b1[e * H_DIM + t];
        sB2[t] = b2[e * H_DIM + t];
    }
    if (t < DA) sB3[t] = b3[e * OUT_DIM + t];
    __syncthreads();

    // staging roles (1024 threads)
    const int arow = t >> 3, aseg = t & 7;     // A: 128 rows x 8 segs of 8 floats
    const int brow = t >> 2, bq = t & 3;       // B: 256 rows x 4 quarters
    const float* frow = features + (size_t)sIdx[arow] * F_DIM;

    const __nv_bfloat16* w1h = &g_W1T_hi[e][0][0];
    const __nv_bfloat16* w1l = &g_W1T_lo[e][0][0];
    const __nv_bfloat16* w2h = &g_W2T_hi[e][0][0];
    const __nv_bfloat16* w2l = &g_W2T_lo[e][0][0];
    const __nv_bfloat16* w3h = &g_W3T_hi[e][0][0];
    const __nv_bfloat16* w3l = &g_W3T_lo[e][0][0];

    float acc[2][4][4];
    #pragma unroll
    for (int mi = 0; mi < 2; mi++)
        #pragma unroll
        for (int ni = 0; ni < 4; ni++)
            #pragma unroll
            for (int c = 0; c < 4; c++) acc[mi][ni][c] = 0.f;

    auto issueB1 = [&](int kc, int buf) {
        const __nv_bfloat16* sh = w1h + (size_t)brow * F_DIM + kc * 64 + bq * 16;
        const __nv_bfloat16* sl = w1l + (size_t)brow * F_DIM + kc * 64 + bq * 16;
        uint32_t dh = sb + (B1_HI(buf) + brow * ASTR + bq * 8) * 4;
        uint32_t dl = sb + (B1_LO(buf) + brow * ASTR + bq * 8) * 4;
        #pragma unroll
        for (int c = 0; c < 2; c++) {
            cpasync16(dh + c * 16, sh + c * 8);
            cpasync16(dl + c * 16, sl + c * 8);
        }
        CP_COMMIT();
    };
    auto stageA = [&](const float4* v4, int buf) {
        uint32_t* dH = sm + A_HI(buf) + arow * ASTR + aseg * 4;
        uint32_t* dL = sm + A_LO(buf) + arow * ASTR + aseg * 4;
        #pragma unroll
        for (int j = 0; j < 2; j++) {
            uint32_t h0, l0, h1, l1;
            split_pack(v4[j].x, v4[j].y, h0, l0);
            split_pack(v4[j].z, v4[j].w, h1, l1);
            dH[j * 2] = h0; dH[j * 2 + 1] = h1;
            dL[j * 2] = l0; dL[j * 2 + 1] = l1;
        }
    };
    auto issueB2 = [&](int kc, int buf) {
        const __nv_bfloat16* sh = w2h + (size_t)brow * H_DIM + kc * 32 + bq * 8;
        const __nv_bfloat16* sl = w2l + (size_t)brow * H_DIM + kc * 32 + bq * 8;
        uint32_t dh = sb + (B2_HI(buf) + brow * B2STR + bq * 4) * 4;
        uint32_t dl = sb + (B2_LO(buf) + brow * B2STR + bq * 4) * 4;
        cpasync16(dh, sh);
        cpasync16(dl, sl);
        CP_COMMIT();
    };

    // ============ Layer 1 pipeline: 8 chunks of K=64 ============
    {
        issueB1(0, 0);
        {
            float4 v4[2];
            const float* src = frow + aseg * 8;
            v4[0] = *(const float4*)(src);
            v4[1] = *(const float4*)(src + 4);
            stageA(v4, 0);
        }
        #pragma unroll 1
        for (int kc = 0; kc < 8; kc++) {
            const int cur = kc & 1, nxt = cur ^ 1;
            CP_WAIT0();
            __syncthreads();
            float4 v4[2];
            if (kc < 7) {
                issueB1(kc + 1, nxt);
                const float* src = frow + (kc + 1) * 64 + aseg * 8;
                v4[0] = *(const float4*)(src);
                v4[1] = *(const float4*)(src + 4);
            }
            mma_chunk_ldsm<ASTR, ASTR, 4>(acc,
                sb + (A_HI(cur) + wrow * 32 * ASTR) * 4 + laneA_A,
                sb + (A_LO(cur) + wrow * 32 * ASTR) * 4 + laneA_A,
                sb + (B1_HI(cur) + wcol * 32 * ASTR) * 4 + laneB_A,
                sb + (B1_LO(cur) + wcol * 32 * ASTR) * 4 + laneB_A);
            if (kc < 7) stageA(v4, nxt);
        }
    }
    __syncthreads();   // layer-1 MMA done: safe to write h (aliases B1) & B2 prologue (aliases A)

    issueB2(0, 0);     // layer-2 prologue overlaps epilogue 1

    // epilogue 1: relu + bias -> h
    #pragma unroll
    for (int mi = 0; mi < 2; mi++) {
        int r0 = wrow * 32 + mi * 16 + gid;
        #pragma unroll
        for (int ni = 0; ni < 4; ni++) {
            int col = wcol * 32 + ni * 8 + 2 * tig;
            int cp  = col >> 1;
            float v0 = fmaxf(acc[mi][ni][0] + sB1[col], 0.f);
            float v1 = fmaxf(acc[mi][ni][1] + sB1[col + 1], 0.f);
            float v2 = fmaxf(acc[mi][ni][2] + sB1[col], 0.f);
            float v3 = fmaxf(acc[mi][ni][3] + sB1[col + 1], 0.f);
            uint32_t hp, lp;
            split_pack(v0, v1, hp, lp);
            hHi[r0 * HSTR + cp] = hp; hLo[r0 * HSTR + cp] = lp;
            split_pack(v2, v3, hp, lp);
            hHi[(r0 + 8) * HSTR + cp] = hp; hLo[(r0 + 8) * HSTR + cp] = lp;
            acc[mi][ni][0] = 0.f; acc[mi][ni][1] = 0.f;
            acc[mi][ni][2] = 0.f; acc[mi][ni][3] = 0.f;
        }
    }

    // ============ Layer 2 pipeline: 8 chunks of K=32 ============
    #pragma unroll 1
    for (int kc = 0; kc < 8; kc++) {
        const int cur = kc & 1, nxt = cur ^ 1;
        CP_WAIT0();
        __syncthreads();
        if (kc < 7) issueB2(kc + 1, nxt);
        mma_chunk_ldsm<HSTR, B2STR, 2>(acc,
            sb + (OFF_HHI + wrow * 32 * HSTR + kc * 16) * 4 + laneA_H,
            sb + (OFF_HLO + wrow * 32 * HSTR + kc * 16) * 4 + laneA_H,
            sb + (B2_HI(cur) + wcol * 32 * B2STR) * 4 + laneB_B2,
            sb + (B2_LO(cur) + wcol * 32 * B2STR) * 4 + laneB_B2);
    }
    __syncthreads();   // layer-2 MMA done: safe to overwrite h and B2 region (W3)

    // stage W3T rows 0..7 (first 8 out cols), K=256
    if (t < 64) {
        int n = t >> 3, i = (t & 7) * 16;
        const uint4* sh = (const uint4*)(w3h + (size_t)n * H_DIM + i * 2);
        const uint4* sl = (const uint4*)(w3l + (size_t)n * H_DIM + i * 2);
        #pragma unroll
        for (int j = 0; j < 4; j++) {
            *(uint4*)&sm[OFF_W3HI + n * HSTR + i + j * 4] = sh[j];
            *(uint4*)&sm[OFF_W3LO + n * HSTR + i + j * 4] = sl[j];
        }
    }

    // epilogue 2: relu + bias -> h (overwrite)
    #pragma unroll
    for (int mi = 0; mi < 2; mi++) {
        int r0 = wrow * 32 + mi * 16 + gid;
        #pragma unroll
        for (int ni = 0; ni < 4; ni++) {
            int col = wcol * 32 + ni * 8 + 2 * tig;
            int cp  = col >> 1;
            float v0 = fmaxf(acc[mi][ni][0] + sB2[col], 0.f);
            float v1 = fmaxf(acc[mi][ni][1] + sB2[col + 1], 0.f);
            float v2 = fmaxf(acc[mi][ni][2] + sB2[col], 0.f);
            float v3 = fmaxf(acc[mi][ni][3] + sB2[col + 1], 0.f);
            uint32_t hp, lp;
            split_pack(v0, v1, hp, lp);
            hHi[r0 * HSTR + cp] = hp; hLo[r0 * HSTR + cp] = lp;
            split_pack(v2, v3, hp, lp);
            hHi[(r0 + 8) * HSTR + cp] = hp; hLo[(r0 + 8) * HSTR + cp] = lp;
        }
    }
    __syncthreads();

    // ============ Layer 3: y = h2 @ W3[:, :8] + b3 (warps 0..7) ============
    if (wid < 8) {
        float acc3[4] = {0.f, 0.f, 0.f, 0.f};
        const uint32_t* pAh = hHi + wid * 16 * HSTR;
        const uint32_t* pAl = hLo + wid * 16 * HSTR;
        const uint32_t* w3H = sm + OFF_W3HI;
        const uint32_t* w3L = sm + OFF_W3LO;
        #pragma unroll
        for (int ks = 0; ks < 16; ks++) {
            const int kb = ks * 8 + tig;
            uint32_t ah[4], al[4];
            ah[0] = pAh[gid * HSTR + kb];       ah[1] = pAh[(gid + 8) * HSTR + kb];
            ah[2] = pAh[gid * HSTR + kb + 4];   ah[3] = pAh[(gid + 8) * HSTR + kb + 4];
            al[0] = pAl[gid * HSTR + kb];       al[1] = pAl[(gid + 8) * HSTR + kb];
            al[2] = pAl[gid * HSTR + kb + 4];   al[3] = pAl[(gid + 8) * HSTR + kb + 4];
            uint32_t bh[2] = { w3H[gid * HSTR + kb], w3H[gid * HSTR + kb + 4] };
            uint32_t bl[2] = { w3L[gid * HSTR + kb], w3L[gid * HSTR + kb + 4] };
            mma16816(acc3, ah, bh);
            mma16816(acc3, ah, bl);
            mma16816(acc3, al, bh);
        }
        int r0 = wid * 16 + gid;
        int c  = 2 * tig;
        if (r0 < nrows) {
            float* o = out + (size_t)sIdx[r0] * DA + c;
            o[0] = acc3[0] + sB3[c];
            o[1] = acc3[1] + sB3[c + 1];
        }
        if (r0 + 8 < nrows) {
            float* o = out + (size_t)sIdx[r0 + 8] * DA + c;
            o[0] = acc3[2] + sB3[c];
            o[1] = acc3[3] + sB3[c + 1];
        }
    }
}

extern "C" void kernel_launch(void* const* d_in, const int* in_sizes, int n_in,
                              void* d_out, int out_size)
{
    const float* features = (const float*)d_in[0];
    const float* W1 = (const float*)d_in[1];
    const float* b1 = (const float*)d_in[2];
    const float* W2 = (const float*)d_in[3];
    const float* b2 = (const float*)d_in[4];
    const float* W3 = (const float*)d_in[5];
    const float* b3 = (const float*)d_in[6];
    const int*   ma = (const int*)d_in[7];
    float* out = (float*)d_out;

    cudaFuncSetAttribute(moe_mma_kernel, cudaFuncAttributeMaxDynamicSharedMemorySize,
                         SMEM_WORDS * 4);

    zero_counts_kernel<<<1, 32>>>();
    scatter_kernel<<<B_ROWS / 256, 256>>>(ma);
    prep_weights<<<dim3(128, E_NUM, 3), dim3(32, 8)>>>(W1, W2, W3);
    moe_mma_kernel<<<dim3(NTILES, E_NUM), 1024, SMEM_WORDS * 4>>>(features, b1, b2, b3, out);
}

// round 12
// speedup vs baseline: 2.5035x; 1.2040x over previous
#include <cuda_runtime.h>
#include <cuda_bf16.h>
#include <cuda_fp16.h>
#include <cstdint>

#define B_ROWS 16384
#define F_DIM  512
#define H_DIM  256
#define E_NUM  8
#define OUT_DIM 32
#define DA     8
#define TM     128
#define NTILES (B_ROWS / TM)   // 128

#define ASTR 36    // b32 stride, 64-bf16 rows (32 words + 4 pad)
#define B2STR 20   // b32 stride, 32-b16 rows (16 words + 4 pad)
#define HSTR 132   // b32 stride, 256-b16 h rows (128 words + 4 pad)

// ---------------- device scratch ----------------
__device__ int g_counts[E_NUM];
__device__ int g_bucket[E_NUM][B_ROWS];

__device__ __align__(16) __nv_bfloat16 g_W1T_hi[E_NUM][H_DIM][F_DIM];
__device__ __align__(16) __nv_bfloat16 g_W1T_lo[E_NUM][H_DIM][F_DIM];
__device__ __align__(16) __half       g_W2T_h [E_NUM][H_DIM][H_DIM];   // fp16 single
__device__ __align__(16) __half       g_W3T_h [E_NUM][OUT_DIM][H_DIM]; // fp16 single

__device__ __forceinline__ void split1(float x, __nv_bfloat16& h, __nv_bfloat16& l) {
    h = __float2bfloat16_rn(x);
    l = __float2bfloat16_rn(x - __bfloat162float(h));
}
__device__ __forceinline__ uint32_t packbf(__nv_bfloat16 a, __nv_bfloat16 b) {
    __nv_bfloat162 t(a, b);
    return *reinterpret_cast<uint32_t*>(&t);
}
__device__ __forceinline__ void split_pack(float v0, float v1, uint32_t& hp, uint32_t& lp) {
    __nv_bfloat16 h0, l0, h1, l1;
    split1(v0, h0, l0); split1(v1, h1, l1);
    hp = packbf(h0, h1);
    lp = packbf(l0, l1);
}
__device__ __forceinline__ uint32_t pack_half2(float v0, float v1) {
    __half2 t = __floats2half2_rn(v0, v1);
    return *reinterpret_cast<uint32_t*>(&t);
}
__device__ __forceinline__ uint32_t smem_u32(const void* p) {
    uint32_t a;
    asm("{ .reg .u64 t; cvta.to.shared.u64 t, %1; cvt.u32.u64 %0, t; }" : "=r"(a) : "l"(p));
    return a;
}
__device__ __forceinline__ void cpasync16(uint32_t dst, const void* src) {
    asm volatile("cp.async.cg.shared.global [%0], [%1], 16;" :: "r"(dst), "l"(src));
}
#define CP_COMMIT() asm volatile("cp.async.commit_group;")
#define CP_WAIT0()  asm volatile("cp.async.wait_group 0;")

__device__ __forceinline__ void mma_bf16(float* d, const uint32_t* a, const uint32_t* b) {
    asm volatile("mma.sync.aligned.m16n8k16.row.col.f32.bf16.bf16.f32 "
        "{%0,%1,%2,%3}, {%4,%5,%6,%7}, {%8,%9}, {%0,%1,%2,%3};"
        : "+f"(d[0]), "+f"(d[1]), "+f"(d[2]), "+f"(d[3])
        : "r"(a[0]), "r"(a[1]), "r"(a[2]), "r"(a[3]), "r"(b[0]), "r"(b[1]));
}
__device__ __forceinline__ void mma_fp16(float* d, const uint32_t* a, const uint32_t* b) {
    asm volatile("mma.sync.aligned.m16n8k16.row.col.f32.f16.f16.f32 "
        "{%0,%1,%2,%3}, {%4,%5,%6,%7}, {%8,%9}, {%0,%1,%2,%3};"
        : "+f"(d[0]), "+f"(d[1]), "+f"(d[2]), "+f"(d[3])
        : "r"(a[0]), "r"(a[1]), "r"(a[2]), "r"(a[3]), "r"(b[0]), "r"(b[1]));
}
__device__ __forceinline__ void ldsm_x4(uint32_t* r, uint32_t addr) {
    asm volatile("ldmatrix.sync.aligned.m8n8.x4.shared.b16 {%0,%1,%2,%3}, [%4];"
        : "=r"(r[0]), "=r"(r[1]), "=r"(r[2]), "=r"(r[3]) : "r"(addr));
}

// Warp-tile (16 rows x 64 cols), bf16x3 split (layer 1).
template<int LDA, int LDB, int NKS>
__device__ __forceinline__ void mma_chunk_bf16x3(
    float acc[8][4],
    uint32_t aHi, uint32_t aLo, uint32_t bHi, uint32_t bLo)
{
    #pragma unroll
    for (int ks = 0; ks < NKS; ks++) {
        uint32_t ah[4], al[4];
        ldsm_x4(ah, aHi + ks * 32);
        ldsm_x4(al, aLo + ks * 32);
        #pragma unroll
        for (int p = 0; p < 4; p++) {
            uint32_t bh[4], bl[4];
            ldsm_x4(bh, bHi + p * (16 * LDB * 4) + ks * 32);
            ldsm_x4(bl, bLo + p * (16 * LDB * 4) + ks * 32);
            #pragma unroll
            for (int q = 0; q < 2; q++) {
                const int ni = p * 2 + q;
                mma_bf16(acc[ni], ah, bh + q * 2);
                mma_bf16(acc[ni], ah, bl + q * 2);
                mma_bf16(acc[ni], al, bh + q * 2);
            }
        }
    }
}

// Warp-tile (16 rows x 64 cols), fp16 single-pass (layer 2).
template<int LDA, int LDB, int NKS>
__device__ __forceinline__ void mma_chunk_fp16(
    float acc[8][4],
    uint32_t aH, uint32_t bH)
{
    #pragma unroll
    for (int ks = 0; ks < NKS; ks++) {
        uint32_t ah[4];
        ldsm_x4(ah, aH + ks * 32);
        #pragma unroll
        for (int p = 0; p < 4; p++) {
            uint32_t bh[4];
            ldsm_x4(bh, bH + p * (16 * LDB * 4) + ks * 32);
            #pragma unroll
            for (int q = 0; q < 2; q++)
                mma_fp16(acc[p * 2 + q], ah, bh + q * 2);
        }
    }
}

// ---------------- prep kernels ----------------
__global__ void zero_counts_kernel() {
    if (threadIdx.x < E_NUM) g_counts[threadIdx.x] = 0;
}
__global__ void scatter_kernel(const int* __restrict__ ma) {
    int i = blockIdx.x * blockDim.x + threadIdx.x;
    if (i < B_ROWS) {
        int e = ma[i];
        int p = atomicAdd(&g_counts[e], 1);
        g_bucket[e][p] = i;
    }
}
__global__ void prep_weights(const float* __restrict__ W1,
                             const float* __restrict__ W2,
                             const float* __restrict__ W3) {
    int z = blockIdx.z, e = blockIdx.y;
    int Kd = (z == 0) ? F_DIM : H_DIM;
    int Nd = (z == 0) ? H_DIM : ((z == 1) ? H_DIM : OUT_DIM);
    int ntn = Nd / 32;
    int tk = (blockIdx.x / ntn) * 32;
    int tn = (blockIdx.x % ntn) * 32;
    if (tk >= Kd) return;
    const float* src = ((z == 0) ? W1 : (z == 1) ? W2 : W3) + (size_t)e * Kd * Nd;
    __shared__ float tile[32][33];
    int tx = threadIdx.x, ty = threadIdx.y;   // 32 x 8
    #pragma unroll
    for (int r = 0; r < 4; r++)
        tile[ty + r * 8][tx] = src[(size_t)(tk + ty + r * 8) * Nd + tn + tx];
    __syncthreads();
    #pragma unroll
    for (int r = 0; r < 4; r++) {
        int n = tn + ty + r * 8, k = tk + tx;
        float v = tile[tx][ty + r * 8];
        if (z == 0) {
            __nv_bfloat16 h, l; split1(v, h, l);
            g_W1T_hi[e][n][k] = h;
            g_W1T_lo[e][n][k] = l;
        } else if (z == 1) {
            g_W2T_h[e][n][k] = __float2half_rn(v);
        } else {
            g_W3T_h[e][n][k] = __float2half_rn(v);
        }
    }
}

// ---------------- smem layout (b32 words) ----------------
#define B1_HI(b) ((b) * 18432)
#define B1_LO(b) (B1_HI(b) + 9216)
#define A_HI(b)  (36864 + (b) * 9216)
#define A_LO(b)  (A_HI(b) + 4608)
#define OFF_HH   0                          // h fp16: 128 x HSTR = 16896 (aliases B1)
#define B2_H(b)  (36864 + (b) * 5632)       // 256 x B2STR = 5120 per buf (aliases A)
#define OFF_W3H  36864                      // 8 x HSTR = 1056 (after layer 2)
#define OFF_IDX  57344
#define OFF_SB1  57472
#define OFF_SB2  57728
#define OFF_SB3  57984
#define SMEM_WORDS 57992     // 231968 bytes

// ---------------- main MMA kernel: 1024 threads, 8x4 warps ----------------
__global__ __launch_bounds__(1024, 1)
void moe_mma_kernel(const float* __restrict__ features,
                    const float* __restrict__ b1,
                    const float* __restrict__ b2,
                    const float* __restrict__ b3,
                    float* __restrict__ out)
{
    const int e = blockIdx.y;
    const int count = g_counts[e];
    const int row0 = blockIdx.x * TM;
    if (row0 >= count) return;
    const int nrows = min(TM, count - row0);

    extern __shared__ uint32_t sm[];
    const uint32_t sb = smem_u32(sm);
    int*   sIdx = (int*)(sm + OFF_IDX);
    float* sB1  = (float*)(sm + OFF_SB1);
    float* sB2  = (float*)(sm + OFF_SB2);
    float* sB3  = (float*)(sm + OFF_SB3);
    uint32_t* hH = sm + OFF_HH;

    const int t    = threadIdx.x;
    const int wid  = t >> 5;
    const int lane = t & 31;
    const int gid  = lane >> 2;
    const int tig  = lane & 3;
    const int wrow = wid & 7;       // 8 row-warps * 16 rows
    const int wcol = wid >> 3;      // 4 col-warps * 64 cols

    // ldmatrix per-lane byte offsets
    const int l8 = lane & 7, lq = lane >> 3;
    const int laneA_A  = ((l8 + 8 * (lq & 1)) * ASTR)  * 4 + (lq >> 1) * 16;
    const int laneA_H  = ((l8 + 8 * (lq & 1)) * HSTR)  * 4 + (lq >> 1) * 16;
    const int laneB_A  = ((l8 + 8 * (lq >> 1)) * ASTR) * 4 + (lq & 1) * 16;
    const int laneB_B2 = ((l8 + 8 * (lq >> 1)) * B2STR) * 4 + (lq & 1) * 16;

    if (t < TM) sIdx[t] = g_bucket[e][row0 + min(t, nrows - 1)];
    if (t < H_DIM) {
        sB1[t] = b1[e * H_DIM + t];
        sB2[t] = b2[e * H_DIM + t];
    }
    if (t < DA) sB3[t] = b3[e * OUT_DIM + t];
    __syncthreads();

    // staging roles (1024 threads)
    const int arow = t >> 3, aseg = t & 7;     // A: 128 rows x 8 segs of 8 floats
    const int brow = t >> 2, bq = t & 3;       // B: 256 rows x 4 quarters
    const float* frow = features + (size_t)sIdx[arow] * F_DIM;

    const __nv_bfloat16* w1h = &g_W1T_hi[e][0][0];
    const __nv_bfloat16* w1l = &g_W1T_lo[e][0][0];
    const __half* w2h = &g_W2T_h[e][0][0];
    const __half* w3h = &g_W3T_h[e][0][0];

    float acc[8][4];
    #pragma unroll
    for (int ni = 0; ni < 8; ni++)
        #pragma unroll
        for (int c = 0; c < 4; c++) acc[ni][c] = 0.f;

    auto issueB1 = [&](int kc, int buf) {
        const __nv_bfloat16* sh = w1h + (size_t)brow * F_DIM + kc * 64 + bq * 16;
        const __nv_bfloat16* sl = w1l + (size_t)brow * F_DIM + kc * 64 + bq * 16;
        uint32_t dh = sb + (B1_HI(buf) + brow * ASTR + bq * 8) * 4;
        uint32_t dl = sb + (B1_LO(buf) + brow * ASTR + bq * 8) * 4;
        #pragma unroll
        for (int c = 0; c < 2; c++) {
            cpasync16(dh + c * 16, sh + c * 8);
            cpasync16(dl + c * 16, sl + c * 8);
        }
        CP_COMMIT();
    };
    auto stageA = [&](const float4* v4, int buf) {
        uint32_t* dH = sm + A_HI(buf) + arow * ASTR + aseg * 4;
        uint32_t* dL = sm + A_LO(buf) + arow * ASTR + aseg * 4;
        #pragma unroll
        for (int j = 0; j < 2; j++) {
            uint32_t h0, l0, h1, l1;
            split_pack(v4[j].x, v4[j].y, h0, l0);
            split_pack(v4[j].z, v4[j].w, h1, l1);
            dH[j * 2] = h0; dH[j * 2 + 1] = h1;
            dL[j * 2] = l0; dL[j * 2 + 1] = l1;
        }
    };
    auto issueB2 = [&](int kc, int buf) {
        const __half* sh = w2h + (size_t)brow * H_DIM + kc * 32 + bq * 8;
        uint32_t dh = sb + (B2_H(buf) + brow * B2STR + bq * 4) * 4;
        cpasync16(dh, sh);
        CP_COMMIT();
    };

    // ============ Layer 1 pipeline: 8 chunks of K=64 (bf16x3) ============
    {
        issueB1(0, 0);
        {
            float4 v4[2];
            const float* src = frow + aseg * 8;
            v4[0] = *(const float4*)(src);
            v4[1] = *(const float4*)(src + 4);
            stageA(v4, 0);
        }
        #pragma unroll 1
        for (int kc = 0; kc < 8; kc++) {
            const int cur = kc & 1, nxt = cur ^ 1;
            CP_WAIT0();
            __syncthreads();
            float4 v4[2];
            if (kc < 7) {
                issueB1(kc + 1, nxt);
                const float* src = frow + (kc + 1) * 64 + aseg * 8;
                v4[0] = *(const float4*)(src);
                v4[1] = *(const float4*)(src + 4);
            }
            mma_chunk_bf16x3<ASTR, ASTR, 4>(acc,
                sb + (A_HI(cur) + wrow * 16 * ASTR) * 4 + laneA_A,
                sb + (A_LO(cur) + wrow * 16 * ASTR) * 4 + laneA_A,
                sb + (B1_HI(cur) + wcol * 64 * ASTR) * 4 + laneB_A,
                sb + (B1_LO(cur) + wcol * 64 * ASTR) * 4 + laneB_A);
            if (kc < 7) stageA(v4, nxt);
        }
    }
    __syncthreads();   // layer-1 MMA done: safe to write h (aliases B1) & B2 prologue (aliases A)

    issueB2(0, 0);     // layer-2 prologue overlaps epilogue 1

    // epilogue 1: relu + bias -> h (fp16)
    {
        int r0 = wrow * 16 + gid;
        #pragma unroll
        for (int ni = 0; ni < 8; ni++) {
            int col = wcol * 64 + ni * 8 + 2 * tig;
            int cp  = col >> 1;
            float v0 = fmaxf(acc[ni][0] + sB1[col], 0.f);
            float v1 = fmaxf(acc[ni][1] + sB1[col + 1], 0.f);
            float v2 = fmaxf(acc[ni][2] + sB1[col], 0.f);
            float v3 = fmaxf(acc[ni][3] + sB1[col + 1], 0.f);
            hH[r0 * HSTR + cp]       = pack_half2(v0, v1);
            hH[(r0 + 8) * HSTR + cp] = pack_half2(v2, v3);
            acc[ni][0] = 0.f; acc[ni][1] = 0.f;
            acc[ni][2] = 0.f; acc[ni][3] = 0.f;
        }
    }

    // ============ Layer 2 pipeline: 8 chunks of K=32 (fp16 single-pass) ============
    #pragma unroll 1
    for (int kc = 0; kc < 8; kc++) {
        const int cur = kc & 1, nxt = cur ^ 1;
        CP_WAIT0();
        __syncthreads();
        if (kc < 7) issueB2(kc + 1, nxt);
        mma_chunk_fp16<HSTR, B2STR, 2>(acc,
            sb + (OFF_HH + wrow * 16 * HSTR + kc * 16) * 4 + laneA_H,
            sb + (B2_H(cur) + wcol * 64 * B2STR) * 4 + laneB_B2);
    }
    __syncthreads();   // layer-2 MMA done: safe to overwrite h and B2 region (W3)

    // stage W3T rows 0..7 (first 8 out cols), K=256, fp16
    if (t < 64) {
        int n = t >> 3, i = (t & 7) * 16;
        const uint4* sh = (const uint4*)(w3h + (size_t)n * H_DIM + i * 2);
        #pragma unroll
        for (int j = 0; j < 4; j++)
            *(uint4*)&sm[OFF_W3H + n * HSTR + i + j * 4] = sh[j];
    }

    // epilogue 2: relu + bias -> h (fp16, overwrite)
    {
        int r0 = wrow * 16 + gid;
        #pragma unroll
        for (int ni = 0; ni < 8; ni++) {
            int col = wcol * 64 + ni * 8 + 2 * tig;
            int cp  = col >> 1;
            float v0 = fmaxf(acc[ni][0] + sB2[col], 0.f);
            float v1 = fmaxf(acc[ni][1] + sB2[col + 1], 0.f);
            float v2 = fmaxf(acc[ni][2] + sB2[col], 0.f);
            float v3 = fmaxf(acc[ni][3] + sB2[col + 1], 0.f);
            hH[r0 * HSTR + cp]       = pack_half2(v0, v1);
            hH[(r0 + 8) * HSTR + cp] = pack_half2(v2, v3);
        }
    }
    __syncthreads();

    // ============ Layer 3: y = h2 @ W3[:, :8] + b3 (fp16, warps 0..7) ============
    if (wid < 8) {
        float acc3[4] = {0.f, 0.f, 0.f, 0.f};
        const uint32_t* pAh = hH + wid * 16 * HSTR;
        const uint32_t* w3H = sm + OFF_W3H;
        #pragma unroll
        for (int ks = 0; ks < 16; ks++) {
            const int kb = ks * 8 + tig;
            uint32_t ah[4];
            ah[0] = pAh[gid * HSTR + kb];       ah[1] = pAh[(gid + 8) * HSTR + kb];
            ah[2] = pAh[gid * HSTR + kb + 4];   ah[3] = pAh[(gid + 8) * HSTR + kb + 4];
            uint32_t bh[2] = { w3H[gid * HSTR + kb], w3H[gid * HSTR + kb + 4] };
            mma_fp16(acc3, ah, bh);
        }
        int r0 = wid * 16 + gid;
        int c  = 2 * tig;
        if (r0 < nrows) {
            float* o = out + (size_t)sIdx[r0] * DA + c;
            o[0] = acc3[0] + sB3[c];
            o[1] = acc3[1] + sB3[c + 1];
        }
        if (r0 + 8 < nrows) {
            float* o = out + (size_t)sIdx[r0 + 8] * DA + c;
            o[0] = acc3[2] + sB3[c];
            o[1] = acc3[3] + sB3[c + 1];
        }
    }
}

extern "C" void kernel_launch(void* const* d_in, const int* in_sizes, int n_in,
                              void* d_out, int out_size)
{
    const float* features = (const float*)d_in[0];
    const float* W1 = (const float*)d_in[1];
    const float* b1 = (const float*)d_in[2];
    const float* W2 = (const float*)d_in[3];
    const float* b2 = (const float*)d_in[4];
    const float* W3 = (const float*)d_in[5];
    const float* b3 = (const float*)d_in[6];
    const int*   ma = (const int*)d_in[7];
    float* out = (float*)d_out;

    cudaFuncSetAttribute(moe_mma_kernel, cudaFuncAttributeMaxDynamicSharedMemorySize,
                         SMEM_WORDS * 4);

    zero_counts_kernel<<<1, 32>>>();
    scatter_kernel<<<B_ROWS / 256, 256>>>(ma);
    prep_weights<<<dim3(128, E_NUM, 3), dim3(32, 8)>>>(W1, W2, W3);
    moe_mma_kernel<<<dim3(NTILES, E_NUM), 1024, SMEM_WORDS * 4>>>(features, b1, b2, b3, out);
}

// round 13
// speedup vs baseline: 3.7186x; 1.4853x over previous
#include <cuda_runtime.h>
#include <cuda_bf16.h>
#include <cuda_fp16.h>
#include <cstdint>

#define B_ROWS 16384
#define F_DIM  512
#define H_DIM  256
#define E_NUM  8
#define OUT_DIM 32
#define DA     8
#define TM     128
#define NTILES (B_ROWS / TM)   // 128

#define ASTR 36    // b32 stride, 64-fp16 rows (32 words + 4 pad)
#define B2STR 20   // b32 stride, 32-fp16 rows (16 words + 4 pad)
#define HSTR 132   // b32 stride, 256-fp16 h rows (128 words + 4 pad)

// ---------------- device scratch ----------------
__device__ int g_counts[E_NUM];
__device__ int g_bucket[E_NUM][B_ROWS];

__device__ __align__(16) __half g_W1T_h[E_NUM][H_DIM][F_DIM];
__device__ __align__(16) __half g_W2T_h[E_NUM][H_DIM][H_DIM];
__device__ __align__(16) __half g_W3T_h[E_NUM][OUT_DIM][H_DIM];

__device__ __forceinline__ uint32_t pack_half2(float v0, float v1) {
    __half2 t = __floats2half2_rn(v0, v1);
    return *reinterpret_cast<uint32_t*>(&t);
}
__device__ __forceinline__ uint32_t smem_u32(const void* p) {
    uint32_t a;
    asm("{ .reg .u64 t; cvta.to.shared.u64 t, %1; cvt.u32.u64 %0, t; }" : "=r"(a) : "l"(p));
    return a;
}
__device__ __forceinline__ void cpasync16(uint32_t dst, const void* src) {
    asm volatile("cp.async.cg.shared.global [%0], [%1], 16;" :: "r"(dst), "l"(src));
}
#define CP_COMMIT() asm volatile("cp.async.commit_group;")
#define CP_WAIT0()  asm volatile("cp.async.wait_group 0;")

__device__ __forceinline__ void mma_fp16(float* d, const uint32_t* a, const uint32_t* b) {
    asm volatile("mma.sync.aligned.m16n8k16.row.col.f32.f16.f16.f32 "
        "{%0,%1,%2,%3}, {%4,%5,%6,%7}, {%8,%9}, {%0,%1,%2,%3};"
        : "+f"(d[0]), "+f"(d[1]), "+f"(d[2]), "+f"(d[3])
        : "r"(a[0]), "r"(a[1]), "r"(a[2]), "r"(a[3]), "r"(b[0]), "r"(b[1]));
}
__device__ __forceinline__ void ldsm_x4(uint32_t* r, uint32_t addr) {
    asm volatile("ldmatrix.sync.aligned.m8n8.x4.shared.b16 {%0,%1,%2,%3}, [%4];"
        : "=r"(r[0]), "=r"(r[1]), "=r"(r[2]), "=r"(r[3]) : "r"(addr));
}

// Warp-tile (16 rows x 64 cols) over NKS*16 K, fp16 single-pass.
template<int LDA, int LDB, int NKS>
__device__ __forceinline__ void mma_chunk_fp16(
    float acc[8][4],
    uint32_t aH, uint32_t bH)
{
    #pragma unroll
    for (int ks = 0; ks < NKS; ks++) {
        uint32_t ah[4];
        ldsm_x4(ah, aH + ks * 32);
        #pragma unroll
        for (int p = 0; p < 4; p++) {
            uint32_t bh[4];
            ldsm_x4(bh, bH + p * (16 * LDB * 4) + ks * 32);
            #pragma unroll
            for (int q = 0; q < 2; q++)
                mma_fp16(acc[p * 2 + q], ah, bh + q * 2);
        }
    }
}

// ---------------- prep kernels ----------------
__global__ void zero_counts_kernel() {
    if (threadIdx.x < E_NUM) g_counts[threadIdx.x] = 0;
}
__global__ void scatter_kernel(const int* __restrict__ ma) {
    int i = blockIdx.x * blockDim.x + threadIdx.x;
    if (i < B_ROWS) {
        int e = ma[i];
        int p = atomicAdd(&g_counts[e], 1);
        g_bucket[e][p] = i;
    }
}
__global__ void prep_weights(const float* __restrict__ W1,
                             const float* __restrict__ W2,
                             const float* __restrict__ W3) {
    int z = blockIdx.z, e = blockIdx.y;
    int Kd = (z == 0) ? F_DIM : H_DIM;
    int Nd = (z == 0) ? H_DIM : ((z == 1) ? H_DIM : OUT_DIM);
    int ntn = Nd / 32;
    int tk = (blockIdx.x / ntn) * 32;
    int tn = (blockIdx.x % ntn) * 32;
    if (tk >= Kd) return;
    const float* src = ((z == 0) ? W1 : (z == 1) ? W2 : W3) + (size_t)e * Kd * Nd;
    __shared__ float tile[32][33];
    int tx = threadIdx.x, ty = threadIdx.y;   // 32 x 8
    #pragma unroll
    for (int r = 0; r < 4; r++)
        tile[ty + r * 8][tx] = src[(size_t)(tk + ty + r * 8) * Nd + tn + tx];
    __syncthreads();
    #pragma unroll
    for (int r = 0; r < 4; r++) {
        int n = tn + ty + r * 8, k = tk + tx;
        __half v = __float2half_rn(tile[tx][ty + r * 8]);
        if (z == 0)      g_W1T_h[e][n][k] = v;
        else if (z == 1) g_W2T_h[e][n][k] = v;
        else             g_W3T_h[e][n][k] = v;
    }
}

// ---------------- smem layout (b32 words) ----------------
#define B1_H(b)  ((b) * 9216)            // 256 x ASTR per buf; [0, 18432)
#define A_H(b)   (18432 + (b) * 4608)    // 128 x ASTR per buf; [18432, 27648)
#define OFF_HH   0                       // h fp16: 128 x HSTR = 16896 (aliases B1)
#define B2_H(b)  (18432 + (b) * 5120)    // 256 x B2STR per buf; [18432, 28672) (aliases A)
#define OFF_W3H  18432                   // 8 x HSTR = 1056 (after layer 2; aliases B2)
#define OFF_IDX  28672
#define OFF_SB1  28800
#define OFF_SB2  29056
#define OFF_SB3  29312
#define SMEM_WORDS 29320     // 117280 bytes

// ---------------- main MMA kernel: 1024 threads, 8x4 warps ----------------
__global__ __launch_bounds__(1024, 1)
void moe_mma_kernel(const float* __restrict__ features,
                    const float* __restrict__ b1,
                    const float* __restrict__ b2,
                    const float* __restrict__ b3,
                    float* __restrict__ out)
{
    const int e = blockIdx.y;
    const int count = g_counts[e];
    const int row0 = blockIdx.x * TM;
    if (row0 >= count) return;
    const int nrows = min(TM, count - row0);

    extern __shared__ uint32_t sm[];
    const uint32_t sb = smem_u32(sm);
    int*   sIdx = (int*)(sm + OFF_IDX);
    float* sB1  = (float*)(sm + OFF_SB1);
    float* sB2  = (float*)(sm + OFF_SB2);
    float* sB3  = (float*)(sm + OFF_SB3);
    uint32_t* hH = sm + OFF_HH;

    const int t    = threadIdx.x;
    const int wid  = t >> 5;
    const int lane = t & 31;
    const int gid  = lane >> 2;
    const int tig  = lane & 3;
    const int wrow = wid & 7;       // 8 row-warps * 16 rows
    const int wcol = wid >> 3;      // 4 col-warps * 64 cols

    // ldmatrix per-lane byte offsets
    const int l8 = lane & 7, lq = lane >> 3;
    const int laneA_A  = ((l8 + 8 * (lq & 1)) * ASTR)  * 4 + (lq >> 1) * 16;
    const int laneA_H  = ((l8 + 8 * (lq & 1)) * HSTR)  * 4 + (lq >> 1) * 16;
    const int laneB_A  = ((l8 + 8 * (lq >> 1)) * ASTR) * 4 + (lq & 1) * 16;
    const int laneB_B2 = ((l8 + 8 * (lq >> 1)) * B2STR) * 4 + (lq & 1) * 16;

    if (t < TM) sIdx[t] = g_bucket[e][row0 + min(t, nrows - 1)];
    if (t < H_DIM) {
        sB1[t] = b1[e * H_DIM + t];
        sB2[t] = b2[e * H_DIM + t];
    }
    if (t < DA) sB3[t] = b3[e * OUT_DIM + t];
    __syncthreads();

    // staging roles (1024 threads)
    const int arow = t >> 3, aseg = t & 7;     // A: 128 rows x 8 segs of 8 floats
    const int brow = t >> 2, bq = t & 3;       // B: 256 rows x 4 quarters
    const float* frow = features + (size_t)sIdx[arow] * F_DIM;

    const __half* w1h = &g_W1T_h[e][0][0];
    const __half* w2h = &g_W2T_h[e][0][0];
    const __half* w3h = &g_W3T_h[e][0][0];

    float acc[8][4];
    #pragma unroll
    for (int ni = 0; ni < 8; ni++)
        #pragma unroll
        for (int c = 0; c < 4; c++) acc[ni][c] = 0.f;

    auto issueB1 = [&](int kc, int buf) {
        const __half* sh = w1h + (size_t)brow * F_DIM + kc * 64 + bq * 16;
        uint32_t dh = sb + (B1_H(buf) + brow * ASTR + bq * 8) * 4;
        #pragma unroll
        for (int c = 0; c < 2; c++)
            cpasync16(dh + c * 16, sh + c * 8);
        CP_COMMIT();
    };
    auto stageA = [&](const float4* v4, int buf) {
        uint32_t* dH = sm + A_H(buf) + arow * ASTR + aseg * 4;
        dH[0] = pack_half2(v4[0].x, v4[0].y);
        dH[1] = pack_half2(v4[0].z, v4[0].w);
        dH[2] = pack_half2(v4[1].x, v4[1].y);
        dH[3] = pack_half2(v4[1].z, v4[1].w);
    };
    auto issueB2 = [&](int kc, int buf) {
        const __half* sh = w2h + (size_t)brow * H_DIM + kc * 32 + bq * 8;
        uint32_t dh = sb + (B2_H(buf) + brow * B2STR + bq * 4) * 4;
        cpasync16(dh, sh);
        CP_COMMIT();
    };

    // ============ Layer 1 pipeline: 8 chunks of K=64 (fp16) ============
    {
        issueB1(0, 0);
        {
            float4 v4[2];
            const float* src = frow + aseg * 8;
            v4[0] = *(const float4*)(src);
            v4[1] = *(const float4*)(src + 4);
            stageA(v4, 0);
        }
        #pragma unroll 1
        for (int kc = 0; kc < 8; kc++) {
            const int cur = kc & 1, nxt = cur ^ 1;
            CP_WAIT0();
            __syncthreads();
            float4 v4[2];
            if (kc < 7) {
                issueB1(kc + 1, nxt);
                const float* src = frow + (kc + 1) * 64 + aseg * 8;
                v4[0] = *(const float4*)(src);
                v4[1] = *(const float4*)(src + 4);
            }
            mma_chunk_fp16<ASTR, ASTR, 4>(acc,
                sb + (A_H(cur) + wrow * 16 * ASTR) * 4 + laneA_A,
                sb + (B1_H(cur) + wcol * 64 * ASTR) * 4 + laneB_A);
            if (kc < 7) stageA(v4, nxt);
        }
    }
    __syncthreads();   // layer-1 MMA done: safe to write h (aliases B1) & B2 prologue (aliases A)

    issueB2(0, 0);     // layer-2 prologue overlaps epilogue 1

    // epilogue 1: relu + bias -> h (fp16)
    {
        int r0 = wrow * 16 + gid;
        #pragma unroll
        for (int ni = 0; ni < 8; ni++) {
            int col = wcol * 64 + ni * 8 + 2 * tig;
            int cp  = col >> 1;
            float v0 = fmaxf(acc[ni][0] + sB1[col], 0.f);
            float v1 = fmaxf(acc[ni][1] + sB1[col + 1], 0.f);
            float v2 = fmaxf(acc[ni][2] + sB1[col], 0.f);
            float v3 = fmaxf(acc[ni][3] + sB1[col + 1], 0.f);
            hH[r0 * HSTR + cp]       = pack_half2(v0, v1);
            hH[(r0 + 8) * HSTR + cp] = pack_half2(v2, v3);
            acc[ni][0] = 0.f; acc[ni][1] = 0.f;
            acc[ni][2] = 0.f; acc[ni][3] = 0.f;
        }
    }

    // ============ Layer 2 pipeline: 8 chunks of K=32 (fp16) ============
    #pragma unroll 1
    for (int kc = 0; kc < 8; kc++) {
        const int cur = kc & 1, nxt = cur ^ 1;
        CP_WAIT0();
        __syncthreads();
        if (kc < 7) issueB2(kc + 1, nxt);
        mma_chunk_fp16<HSTR, B2STR, 2>(acc,
            sb + (OFF_HH + wrow * 16 * HSTR + kc * 16) * 4 + laneA_H,
            sb + (B2_H(cur) + wcol * 64 * B2STR) * 4 + laneB_B2);
    }
    __syncthreads();   // layer-2 MMA done: safe to overwrite h and B2 region (W3)

    // stage W3T rows 0..7 (first 8 out cols), K=256, fp16
    if (t < 64) {
        int n = t >> 3, i = (t & 7) * 16;
        const uint4* sh = (const uint4*)(w3h + (size_t)n * H_DIM + i * 2);
        #pragma unroll
        for (int j = 0; j < 4; j++)
            *(uint4*)&sm[OFF_W3H + n * HSTR + i + j * 4] = sh[j];
    }

    // epilogue 2: relu + bias -> h (fp16, overwrite)
    {
        int r0 = wrow * 16 + gid;
        #pragma unroll
        for (int ni = 0; ni < 8; ni++) {
            int col = wcol * 64 + ni * 8 + 2 * tig;
            int cp  = col >> 1;
            float v0 = fmaxf(acc[ni][0] + sB2[col], 0.f);
            float v1 = fmaxf(acc[ni][1] + sB2[col + 1], 0.f);
            float v2 = fmaxf(acc[ni][2] + sB2[col], 0.f);
            float v3 = fmaxf(acc[ni][3] + sB2[col + 1], 0.f);
            hH[r0 * HSTR + cp]       = pack_half2(v0, v1);
            hH[(r0 + 8) * HSTR + cp] = pack_half2(v2, v3);
        }
    }
    __syncthreads();

    // ============ Layer 3: y = h2 @ W3[:, :8] + b3 (fp16, warps 0..7) ============
    if (wid < 8) {
        float acc3[4] = {0.f, 0.f, 0.f, 0.f};
        const uint32_t* pAh = hH + wid * 16 * HSTR;
        const uint32_t* w3H = sm + OFF_W3H;
        #pragma unroll
        for (int ks = 0; ks < 16; ks++) {
            const int kb = ks * 8 + tig;
            uint32_t ah[4];
            ah[0] = pAh[gid * HSTR + kb];       ah[1] = pAh[(gid + 8) * HSTR + kb];
            ah[2] = pAh[gid * HSTR + kb + 4];   ah[3] = pAh[(gid + 8) * HSTR + kb + 4];
            uint32_t bh[2] = { w3H[gid * HSTR + kb], w3H[gid * HSTR + kb + 4] };
            mma_fp16(acc3, ah, bh);
        }
        int r0 = wid * 16 + gid;
        int c  = 2 * tig;
        if (r0 < nrows) {
            float* o = out + (size_t)sIdx[r0] * DA + c;
            o[0] = acc3[0] + sB3[c];
            o[1] = acc3[1] + sB3[c + 1];
        }
        if (r0 + 8 < nrows) {
            float* o = out + (size_t)sIdx[r0 + 8] * DA + c;
            o[0] = acc3[2] + sB3[c];
            o[1] = acc3[3] + sB3[c + 1];
        }
    }
}

extern "C" void kernel_launch(void* const* d_in, const int* in_sizes, int n_in,
                              void* d_out, int out_size)
{
    const float* features = (const float*)d_in[0];
    const float* W1 = (const float*)d_in[1];
    const float* b1 = (const float*)d_in[2];
    const float* W2 = (const float*)d_in[3];
    const float* b2 = (const float*)d_in[4];
    const float* W3 = (const float*)d_in[5];
    const float* b3 = (const float*)d_in[6];
    const int*   ma = (const int*)d_in[7];
    float* out = (float*)d_out;

    cudaFuncSetAttribute(moe_mma_kernel, cudaFuncAttributeMaxDynamicSharedMemorySize,
                         SMEM_WORDS * 4);

    zero_counts_kernel<<<1, 32>>>();
    scatter_kernel<<<B_ROWS / 256, 256>>>(ma);
    prep_weights<<<dim3(128, E_NUM, 3), dim3(32, 8)>>>(W1, W2, W3);
    moe_mma_kernel<<<dim3(NTILES, E_NUM), 1024, SMEM_WORDS * 4>>>(features, b1, b2, b3, out);
}